// round 15
// baseline (speedup 1.0000x reference)
#include <cuda_runtime.h>
#include <cuda_bf16.h>
#include <math.h>
#include <cstdint>

// Problem constants
#define N0c 1500000
#define N1c 200000
#define N2c 20000
#define Bc  4096
#define E0c 2000000
#define E1c 200000
#define E2c 20480
#define DIN 100
#define DH  256
#define DOUT 47

// ---------------- scratch (static device globals; no allocation) -------------
__device__ float g_mean0[(size_t)N1c * DIN];
__device__ float g_h0  [(size_t)N1c * DH];
__device__ float g_mean1[(size_t)N2c * DH];
__device__ float g_h1  [(size_t)N2c * DH];
__device__ float g_mean2[(size_t)Bc * DH];
__device__ int   g_cnt [N1c];
__device__ int   g_off [N1c + 1];
__device__ int   g_cur [N1c];
__device__ int   g_eidx[E0c];
__device__ int   g_csum[256];
__device__ int   g_coff[256];
// packed B fragments: [kstep][ntile(32)][lane(32)] = uint4{hi0,hi1,lo0,lo1}
__device__ uint4 g_wfr0[13 * 32 * 32];   // layer0: 13 k-steps (K=208)
__device__ uint4 g_wfr1[32 * 32 * 32];   // layer1: 32 k-steps (K=512)

// bf16 mma.sync (baseline PTX feature; compiles for plain sm_103 target)
#define MMA16816(d, a, b0, b1) \
    asm volatile("mma.sync.aligned.m16n8k16.row.col.f32.bf16.bf16.f32 " \
        "{%0,%1,%2,%3}, {%4,%5,%6,%7}, {%8,%9}, {%0,%1,%2,%3};" \
        : "+f"((d)[0]), "+f"((d)[1]), "+f"((d)[2]), "+f"((d)[3]) \
        : "r"((a)[0]), "r"((a)[1]), "r"((a)[2]), "r"((a)[3]), \
          "r"(b0), "r"(b1))

__device__ __forceinline__ unsigned short bf16_bits(float x) {
    __nv_bfloat16 h = __float2bfloat16(x);
    return *(unsigned short*)&h;
}
__device__ __forceinline__ float bf16_val(unsigned short u) {
    __nv_bfloat16 h = *(__nv_bfloat16*)&u;
    return __bfloat162float(h);
}

// ---------------- CSR build kernels ------------------------------------------
__global__ void zero_int_kernel(int* __restrict__ p, int n) {
    int i = blockIdx.x * blockDim.x + threadIdx.x;
    if (i < n) p[i] = 0;
}
__global__ void hist_kernel(const int* __restrict__ dst, int E, int* __restrict__ cnt) {
    int i = blockIdx.x * blockDim.x + threadIdx.x;
    if (i < E) atomicAdd(&cnt[dst[i]], 1);
}
__global__ void scan_chunk_sum(const int* __restrict__ cnt, int n, int* __restrict__ csum) {
    __shared__ int sh[256];
    int c = blockIdx.x, t = threadIdx.x;
    int base = c * 1024 + t * 4;
    int s = 0;
#pragma unroll
    for (int i = 0; i < 4; i++) { int idx = base + i; if (idx < n) s += cnt[idx]; }
    sh[t] = s; __syncthreads();
    for (int ofs = 128; ofs > 0; ofs >>= 1) {
        if (t < ofs) sh[t] += sh[t + ofs];
        __syncthreads();
    }
    if (t == 0) csum[c] = sh[0];
}
// Parallel single-block exclusive scan over chunk sums (nchunks <= 256).
__global__ void scan_chunks_par(const int* __restrict__ csum, int* __restrict__ coff,
                                int nchunks, int* __restrict__ off, int n) {
    __shared__ int sh[256];
    int t = threadIdx.x;
    int v = (t < nchunks) ? csum[t] : 0;
    sh[t] = v; __syncthreads();
    for (int ofs = 1; ofs < 256; ofs <<= 1) {
        int add = (t >= ofs) ? sh[t - ofs] : 0;
        __syncthreads();
        sh[t] += add;
        __syncthreads();
    }
    if (t < nchunks) coff[t] = sh[t] - v;     // exclusive
    if (t == 255) off[n] = sh[nchunks - 1];
}
__global__ void scan_write(const int* __restrict__ cnt, int n, const int* __restrict__ coff,
                           int* __restrict__ off, int* __restrict__ cur) {
    __shared__ int sh[256];
    int c = blockIdx.x, t = threadIdx.x;
    int base = c * 1024 + t * 4;
    int v[4]; int s = 0;
#pragma unroll
    for (int i = 0; i < 4; i++) {
        int idx = base + i;
        v[i] = (idx < n) ? cnt[idx] : 0;
        s += v[i];
    }
    sh[t] = s; __syncthreads();
    for (int ofs = 1; ofs < 256; ofs <<= 1) {
        int add = (t >= ofs) ? sh[t - ofs] : 0;
        __syncthreads();
        sh[t] += add;
        __syncthreads();
    }
    int excl = (t == 0) ? 0 : sh[t - 1];
    int run = coff[c] + excl;
#pragma unroll
    for (int i = 0; i < 4; i++) {
        int idx = base + i;
        if (idx < n) { off[idx] = run; cur[idx] = run; run += v[i]; }
    }
}
__global__ void scatter_kernel(const int* __restrict__ src, const int* __restrict__ dst, int E,
                               int* __restrict__ cur, int* __restrict__ eidx) {
    int i = blockIdx.x * blockDim.x + threadIdx.x;
    if (i < E) {
        int p = atomicAdd(&cur[dst[i]], 1);
        eidx[p] = src[i];
    }
}

// ---------------- aggregation (unchanged, verified) ---------------------------
template <int D>
__global__ void aggregate_mean(const float* __restrict__ X,
                               const int* __restrict__ off, const int* __restrict__ eidx,
                               float* __restrict__ outp, int n_dst) {
    constexpr int NV4 = D / 4;
    constexpr int NSEG = (NV4 + 31) / 32;
    int node = blockIdx.x * (blockDim.x >> 5) + (threadIdx.x >> 5);
    if (node >= n_dst) return;
    int lane = threadIdx.x & 31;
    int s = off[node], e = off[node + 1];
    int deg = e - s;
    float4 acc[NSEG];
#pragma unroll
    for (int i = 0; i < NSEG; i++) acc[i] = make_float4(0.f, 0.f, 0.f, 0.f);
    int j = s;
    for (; j + 1 < e; j += 2) {
        int i0 = __ldg(&eidx[j]);
        int i1 = __ldg(&eidx[j + 1]);
        const float4* r0 = (const float4*)(X + (size_t)i0 * D);
        const float4* r1 = (const float4*)(X + (size_t)i1 * D);
        float4 v0[NSEG], v1[NSEG];
#pragma unroll
        for (int i = 0; i < NSEG; i++) {
            int g = lane + i * 32;
            if (g < NV4) v0[i] = __ldg(&r0[g]);
        }
#pragma unroll
        for (int i = 0; i < NSEG; i++) {
            int g = lane + i * 32;
            if (g < NV4) v1[i] = __ldg(&r1[g]);
        }
#pragma unroll
        for (int i = 0; i < NSEG; i++) {
            int g = lane + i * 32;
            if (g < NV4) {
                acc[i].x += v0[i].x + v1[i].x;
                acc[i].y += v0[i].y + v1[i].y;
                acc[i].z += v0[i].z + v1[i].z;
                acc[i].w += v0[i].w + v1[i].w;
            }
        }
    }
    if (j < e) {
        const float4* row = (const float4*)(X + (size_t)__ldg(&eidx[j]) * D);
#pragma unroll
        for (int i = 0; i < NSEG; i++) {
            int g = lane + i * 32;
            if (g < NV4) {
                float4 v = __ldg(&row[g]);
                acc[i].x += v.x; acc[i].y += v.y; acc[i].z += v.z; acc[i].w += v.w;
            }
        }
    }
    float inv = (deg > 0) ? 1.f / (float)deg : 0.f;
    float4* orow = (float4*)(outp + (size_t)node * D);
#pragma unroll
    for (int i = 0; i < NSEG; i++) {
        int g = lane + i * 32;
        if (g < NV4) {
            float4 v;
            v.x = acc[i].x * inv; v.y = acc[i].y * inv;
            v.z = acc[i].z * inv; v.w = acc[i].w * inv;
            orow[g] = v;
        }
    }
}

// ------- weight pre-pack: fp32 -> bf16 hi/lo B-fragments (mma layout) ---------
__global__ void pack_w_mma(const float* __restrict__ Wl, int K1,
                           const float* __restrict__ Wr, int K2,
                           uint4* __restrict__ out, int nsteps) {
    int idx = blockIdx.x * blockDim.x + threadIdx.x;
    if (idx >= nsteps * 1024) return;
    int lane = idx & 31, nt = (idx >> 5) & 31, s = idx >> 10;
    int g = lane >> 2, tg = lane & 3;
    int o = nt * 8 + g;
    auto getw = [&](int f) -> float {
        if (f < K1) return Wl[(size_t)f * 256 + o];
        f -= K1;
        if (f < K2) return Wr[(size_t)f * 256 + o];
        return 0.f;
    };
    int k0 = s * 16 + tg * 2;
    float w[4] = { getw(k0), getw(k0 + 1), getw(k0 + 8), getw(k0 + 9) };
    unsigned short hb[4], lb[4];
#pragma unroll
    for (int i = 0; i < 4; i++) {
        hb[i] = bf16_bits(w[i]);
        lb[i] = bf16_bits(w[i] - bf16_val(hb[i]));
    }
    uint4 r;
    r.x = ((unsigned)hb[1] << 16) | hb[0];
    r.y = ((unsigned)hb[3] << 16) | hb[2];
    r.z = ((unsigned)lb[1] << 16) | lb[0];
    r.w = ((unsigned)lb[3] << 16) | lb[2];
    out[idx] = r;
}

// ---------- bf16 mma.sync dual GEMM: C = relu([A1|A2|pad] @ W + b) ------------
// Block 64(M) x 256(N), 256 threads / 8 warps; warp w owns cols 32w..32w+31.
// Per k16-step: stage A hi/lo bf16 in smem, each warp 4(mt)x4(nt)x3 terms MMA.
// R10 structure; occupancy 2 so a co-resident CTA's MMA phase hides this
// CTA's staging latency (scheduler-level double buffering, no code change).
__global__ __launch_bounds__(256, 2)
void mma_gemm_relu(const float* __restrict__ A1, int K1,
                   const float* __restrict__ A2, int K2, int nsteps,
                   const uint4* __restrict__ Wfr,
                   const float* __restrict__ bias,
                   float* __restrict__ Cout, int M) {
    __shared__ __align__(16) unsigned short sAhi[64][16];
    __shared__ __align__(16) unsigned short sAlo[64][16];
    __shared__ float sbias[256];
    int tid = threadIdx.x;
    int wid = tid >> 5, lane = tid & 31;
    int g = lane >> 2, tg = lane & 3;
    int m0 = blockIdx.x * 64;
    sbias[tid] = bias[tid];

    float acc[4][4][4];
#pragma unroll
    for (int a = 0; a < 4; a++)
#pragma unroll
        for (int b = 0; b < 4; b++)
#pragma unroll
            for (int c = 0; c < 4; c++) acc[a][b][c] = 0.f;

    int srow = tid >> 2;           // staging row 0..63
    int kq = (tid & 3) * 4;        // staging k quad 0,4,8,12
    int grow = m0 + srow;
    bool gv = grow < M;
    const float* a1row = A1 + (size_t)grow * K1;
    const float* a2row = A2 + (size_t)grow * K2;

    for (int s = 0; s < nsteps; s++) {
        __syncthreads();           // frags of prev step consumed
        int f = s * 16 + kq;
        float4 v = make_float4(0.f, 0.f, 0.f, 0.f);
        if (gv) {
            if (f + 4 <= K1) v = *(const float4*)(a1row + f);
            else if (f >= K1 && f + 4 <= K1 + K2) v = *(const float4*)(a2row + (f - K1));
        }
        float fv[4] = { v.x, v.y, v.z, v.w };
#pragma unroll
        for (int j = 0; j < 4; j++) {
            unsigned short hb = bf16_bits(fv[j]);
            sAhi[srow][kq + j] = hb;
            sAlo[srow][kq + j] = bf16_bits(fv[j] - bf16_val(hb));
        }
        __syncthreads();

        // A fragments (PTX m16n8k16 row-major layout)
        unsigned ahi[4][4], alo[4][4];
#pragma unroll
        for (int mt = 0; mt < 4; mt++) {
            int r0 = mt * 16 + g, r1 = r0 + 8;
            ahi[mt][0] = *(const unsigned*)&sAhi[r0][tg * 2];
            ahi[mt][1] = *(const unsigned*)&sAhi[r1][tg * 2];
            ahi[mt][2] = *(const unsigned*)&sAhi[r0][tg * 2 + 8];
            ahi[mt][3] = *(const unsigned*)&sAhi[r1][tg * 2 + 8];
            alo[mt][0] = *(const unsigned*)&sAlo[r0][tg * 2];
            alo[mt][1] = *(const unsigned*)&sAlo[r1][tg * 2];
            alo[mt][2] = *(const unsigned*)&sAlo[r0][tg * 2 + 8];
            alo[mt][3] = *(const unsigned*)&sAlo[r1][tg * 2 + 8];
        }

#pragma unroll
        for (int ntl = 0; ntl < 4; ntl++) {
            int nt = wid * 4 + ntl;
            uint4 b = __ldg(&Wfr[((size_t)s * 32 + nt) * 32 + lane]);
#pragma unroll
            for (int mt = 0; mt < 4; mt++) {
                MMA16816(acc[mt][ntl], ahi[mt], b.x, b.y);   // hi @ Whi
                MMA16816(acc[mt][ntl], alo[mt], b.x, b.y);   // lo @ Whi
                MMA16816(acc[mt][ntl], ahi[mt], b.z, b.w);   // hi @ Wlo
            }
        }
    }

    // epilogue: bias + relu, fp32 out
#pragma unroll
    for (int mt = 0; mt < 4; mt++) {
        int r0 = m0 + mt * 16 + g, r1 = r0 + 8;
#pragma unroll
        for (int ntl = 0; ntl < 4; ntl++) {
            int col = (wid * 4 + ntl) * 8 + tg * 2;
            float b0 = sbias[col], b1 = sbias[col + 1];
            if (r0 < M) {
                float2 o;
                o.x = fmaxf(acc[mt][ntl][0] + b0, 0.f);
                o.y = fmaxf(acc[mt][ntl][1] + b1, 0.f);
                *(float2*)(Cout + (size_t)r0 * 256 + col) = o;
            }
            if (r1 < M) {
                float2 o;
                o.x = fmaxf(acc[mt][ntl][2] + b0, 0.f);
                o.y = fmaxf(acc[mt][ntl][3] + b1, 0.f);
                *(float2*)(Cout + (size_t)r1 * 256 + col) = o;
            }
        }
    }
}

// ---------------- final layer: small GEMM + bias + log_softmax ----------------
__global__ void final_logsoftmax(const float* __restrict__ mean2, const float* __restrict__ h1,
                                 const float* __restrict__ Wl2, const float* __restrict__ Wr2,
                                 const float* __restrict__ b2, float* __restrict__ out) {
    __shared__ float sa[DH], sb[DH], red[64];
    int row = blockIdx.x, t = threadIdx.x;
    for (int i = t; i < DH; i += 64) {
        sa[i] = mean2[(size_t)row * DH + i];
        sb[i] = h1[(size_t)row * DH + i];
    }
    __syncthreads();
    float cv = 0.f;
    if (t < DOUT) {
        cv = b2[t];
#pragma unroll 4
        for (int k = 0; k < DH; k++)
            cv = fmaf(sa[k], __ldg(&Wl2[k * DOUT + t]),
                      fmaf(sb[k], __ldg(&Wr2[k * DOUT + t]), cv));
    }
    red[t] = (t < DOUT) ? cv : -3.4e38f;
    __syncthreads();
    for (int s = 32; s > 0; s >>= 1) {
        if (t < s) red[t] = fmaxf(red[t], red[t + s]);
        __syncthreads();
    }
    float mx = red[0];
    __syncthreads();
    red[t] = (t < DOUT) ? expf(cv - mx) : 0.f;
    __syncthreads();
    for (int s = 32; s > 0; s >>= 1) {
        if (t < s) red[t] += red[t + s];
        __syncthreads();
    }
    float lse = logf(red[0]) + mx;
    if (t < DOUT) out[(size_t)row * DOUT + t] = cv - lse;
}

// ---------------- host orchestration -----------------------------------------
static inline int ceil_div(int a, int b) { return (a + b - 1) / b; }

static void build_csr(const int* src, const int* dst, int E, int n,
                      int* cnt, int* off, int* cur, int* eidx, int* csum, int* coff) {
    int nch = ceil_div(n, 1024);
    zero_int_kernel<<<ceil_div(n, 256), 256>>>(cnt, n);
    hist_kernel<<<ceil_div(E, 256), 256>>>(dst, E, cnt);
    scan_chunk_sum<<<nch, 256>>>(cnt, n, csum);
    scan_chunks_par<<<1, 256>>>(csum, coff, nch, off, n);
    scan_write<<<nch, 256>>>(cnt, n, coff, off, cur);
    scatter_kernel<<<ceil_div(E, 256), 256>>>(src, dst, E, cur, eidx);
}

extern "C" void kernel_launch(void* const* d_in, const int* in_sizes, int n_in,
                              void* d_out, int out_size) {
    const float* x   = (const float*)d_in[0];
    const int* src0  = (const int*)d_in[1];
    const int* dst0  = (const int*)d_in[2];
    const int* src1  = (const int*)d_in[3];
    const int* dst1  = (const int*)d_in[4];
    const int* src2  = (const int*)d_in[5];
    const int* dst2  = (const int*)d_in[6];
    const float* Wl0 = (const float*)d_in[7];
    const float* Wr0 = (const float*)d_in[8];
    const float* b0  = (const float*)d_in[9];
    const float* Wl1 = (const float*)d_in[10];
    const float* Wr1 = (const float*)d_in[11];
    const float* b1  = (const float*)d_in[12];
    const float* Wl2 = (const float*)d_in[13];
    const float* Wr2 = (const float*)d_in[14];
    const float* b2  = (const float*)d_in[15];
    float* out = (float*)d_out;

    float *mean0, *h0, *mean1, *h1, *mean2;
    int *cnt, *off, *cur, *eidx, *csum, *coff;
    uint4 *wfr0, *wfr1;
    cudaGetSymbolAddress((void**)&mean0, g_mean0);
    cudaGetSymbolAddress((void**)&h0,    g_h0);
    cudaGetSymbolAddress((void**)&mean1, g_mean1);
    cudaGetSymbolAddress((void**)&h1,    g_h1);
    cudaGetSymbolAddress((void**)&mean2, g_mean2);
    cudaGetSymbolAddress((void**)&cnt,   g_cnt);
    cudaGetSymbolAddress((void**)&off,   g_off);
    cudaGetSymbolAddress((void**)&cur,   g_cur);
    cudaGetSymbolAddress((void**)&eidx,  g_eidx);
    cudaGetSymbolAddress((void**)&csum,  g_csum);
    cudaGetSymbolAddress((void**)&coff,  g_coff);
    cudaGetSymbolAddress((void**)&wfr0,  g_wfr0);
    cudaGetSymbolAddress((void**)&wfr1,  g_wfr1);

    // weight fragment pre-pack (once per launch)
    pack_w_mma<<<ceil_div(13 * 1024, 256), 256>>>(Wl0, DIN, Wr0, DIN, wfr0, 13);
    pack_w_mma<<<ceil_div(32 * 1024, 256), 256>>>(Wl1, DH, Wr1, DH, wfr1, 32);

    // ---- layer 0 ----
    build_csr(src0, dst0, E0c, N1c, cnt, off, cur, eidx, csum, coff);
    aggregate_mean<DIN><<<ceil_div(N1c, 8), 256>>>(x, off, eidx, mean0, N1c);
    mma_gemm_relu<<<ceil_div(N1c, 64), 256>>>(mean0, DIN, x, DIN, 13, wfr0, b0, h0, N1c);

    // ---- layer 1 ----
    build_csr(src1, dst1, E1c, N2c, cnt, off, cur, eidx, csum, coff);
    aggregate_mean<DH><<<ceil_div(N2c, 8), 256>>>(h0, off, eidx, mean1, N2c);
    mma_gemm_relu<<<ceil_div(N2c, 64), 256>>>(mean1, DH, h0, DH, 32, wfr1, b1, h1, N2c);

    // ---- layer 2 + log_softmax ----
    build_csr(src2, dst2, E2c, Bc, cnt, off, cur, eidx, csum, coff);
    aggregate_mean<DH><<<ceil_div(Bc, 8), 256>>>(h1, off, eidx, mean2, Bc);
    final_logsoftmax<<<Bc, 64>>>(mean2, h1, Wl2, Wr2, b2, out);
}

// round 16
// speedup vs baseline: 1.0106x; 1.0106x over previous
#include <cuda_runtime.h>
#include <cuda_bf16.h>
#include <math.h>
#include <cstdint>

// Problem constants
#define N0c 1500000
#define N1c 200000
#define N2c 20000
#define Bc  4096
#define E0c 2000000
#define E1c 200000
#define E2c 20480
#define DIN 100
#define DH  256
#define DOUT 47

// ---------------- scratch (static device globals; no allocation) -------------
__device__ float g_mean0[(size_t)N1c * DIN];
__device__ float g_h0  [(size_t)N1c * DH];
__device__ float g_mean1[(size_t)N2c * DH];
__device__ float g_h1  [(size_t)N2c * DH];
__device__ float g_mean2[(size_t)Bc * DH];
__device__ int   g_cnt [N1c];    // INVARIANT: zero before and after each kernel_launch
__device__ int   g_off [N1c + 1];
__device__ int   g_cur [N1c];
__device__ int   g_eidx[E0c];
__device__ int   g_csum[256];
__device__ int   g_coff[256];
// packed B fragments: [kstep][ntile(32)][lane(32)] = uint4{hi0,hi1,lo0,lo1}
__device__ uint4 g_wfr0[13 * 32 * 32];   // layer0: 13 k-steps (K=208)
__device__ uint4 g_wfr1[32 * 32 * 32];   // layer1: 32 k-steps (K=512)

// bf16 mma.sync (baseline PTX feature; compiles for plain sm_103 target)
#define MMA16816(d, a, b0, b1) \
    asm volatile("mma.sync.aligned.m16n8k16.row.col.f32.bf16.bf16.f32 " \
        "{%0,%1,%2,%3}, {%4,%5,%6,%7}, {%8,%9}, {%0,%1,%2,%3};" \
        : "+f"((d)[0]), "+f"((d)[1]), "+f"((d)[2]), "+f"((d)[3]) \
        : "r"((a)[0]), "r"((a)[1]), "r"((a)[2]), "r"((a)[3]), \
          "r"(b0), "r"(b1))

__device__ __forceinline__ unsigned short bf16_bits(float x) {
    __nv_bfloat16 h = __float2bfloat16(x);
    return *(unsigned short*)&h;
}
__device__ __forceinline__ float bf16_val(unsigned short u) {
    __nv_bfloat16 h = *(__nv_bfloat16*)&u;
    return __bfloat162float(h);
}

// ---------------- CSR build kernels ------------------------------------------
__global__ void hist_kernel(const int* __restrict__ dst, int E, int* __restrict__ cnt) {
    int i = blockIdx.x * blockDim.x + threadIdx.x;
    if (i < E) atomicAdd(&cnt[dst[i]], 1);
}
__global__ void scan_chunk_sum(const int* __restrict__ cnt, int n, int* __restrict__ csum) {
    __shared__ int sh[256];
    int c = blockIdx.x, t = threadIdx.x;
    int base = c * 1024 + t * 4;
    int s = 0;
#pragma unroll
    for (int i = 0; i < 4; i++) { int idx = base + i; if (idx < n) s += cnt[idx]; }
    sh[t] = s; __syncthreads();
    for (int ofs = 128; ofs > 0; ofs >>= 1) {
        if (t < ofs) sh[t] += sh[t + ofs];
        __syncthreads();
    }
    if (t == 0) csum[c] = sh[0];
}
// Parallel single-block exclusive scan over chunk sums (nchunks <= 256).
__global__ void scan_chunks_par(const int* __restrict__ csum, int* __restrict__ coff,
                                int nchunks, int* __restrict__ off, int n) {
    __shared__ int sh[256];
    int t = threadIdx.x;
    int v = (t < nchunks) ? csum[t] : 0;
    sh[t] = v; __syncthreads();
    for (int ofs = 1; ofs < 256; ofs <<= 1) {
        int add = (t >= ofs) ? sh[t - ofs] : 0;
        __syncthreads();
        sh[t] += add;
        __syncthreads();
    }
    if (t < nchunks) coff[t] = sh[t] - v;     // exclusive
    if (t == 255) off[n] = sh[nchunks - 1];
}
// Writes per-element offsets AND zeroes cnt after reading (restores the
// cnt==0 invariant so no separate zeroing launch is needed per replay).
__global__ void scan_write(int* __restrict__ cnt, int n, const int* __restrict__ coff,
                           int* __restrict__ off, int* __restrict__ cur) {
    __shared__ int sh[256];
    int c = blockIdx.x, t = threadIdx.x;
    int base = c * 1024 + t * 4;
    int v[4]; int s = 0;
#pragma unroll
    for (int i = 0; i < 4; i++) {
        int idx = base + i;
        v[i] = (idx < n) ? cnt[idx] : 0;
        if (idx < n) cnt[idx] = 0;            // restore invariant
        s += v[i];
    }
    sh[t] = s; __syncthreads();
    for (int ofs = 1; ofs < 256; ofs <<= 1) {
        int add = (t >= ofs) ? sh[t - ofs] : 0;
        __syncthreads();
        sh[t] += add;
        __syncthreads();
    }
    int excl = (t == 0) ? 0 : sh[t - 1];
    int run = coff[c] + excl;
#pragma unroll
    for (int i = 0; i < 4; i++) {
        int idx = base + i;
        if (idx < n) { off[idx] = run; cur[idx] = run; run += v[i]; }
    }
}
__global__ void scatter_kernel(const int* __restrict__ src, const int* __restrict__ dst, int E,
                               int* __restrict__ cur, int* __restrict__ eidx) {
    int i = blockIdx.x * blockDim.x + threadIdx.x;
    if (i < E) {
        int p = atomicAdd(&cur[dst[i]], 1);
        eidx[p] = src[i];
    }
}

// ---------------- aggregation (unchanged, verified) ---------------------------
template <int D>
__global__ void aggregate_mean(const float* __restrict__ X,
                               const int* __restrict__ off, const int* __restrict__ eidx,
                               float* __restrict__ outp, int n_dst) {
    constexpr int NV4 = D / 4;
    constexpr int NSEG = (NV4 + 31) / 32;
    int node = blockIdx.x * (blockDim.x >> 5) + (threadIdx.x >> 5);
    if (node >= n_dst) return;
    int lane = threadIdx.x & 31;
    int s = off[node], e = off[node + 1];
    int deg = e - s;
    float4 acc[NSEG];
#pragma unroll
    for (int i = 0; i < NSEG; i++) acc[i] = make_float4(0.f, 0.f, 0.f, 0.f);
    int j = s;
    for (; j + 1 < e; j += 2) {
        int i0 = __ldg(&eidx[j]);
        int i1 = __ldg(&eidx[j + 1]);
        const float4* r0 = (const float4*)(X + (size_t)i0 * D);
        const float4* r1 = (const float4*)(X + (size_t)i1 * D);
        float4 v0[NSEG], v1[NSEG];
#pragma unroll
        for (int i = 0; i < NSEG; i++) {
            int g = lane + i * 32;
            if (g < NV4) v0[i] = __ldg(&r0[g]);
        }
#pragma unroll
        for (int i = 0; i < NSEG; i++) {
            int g = lane + i * 32;
            if (g < NV4) v1[i] = __ldg(&r1[g]);
        }
#pragma unroll
        for (int i = 0; i < NSEG; i++) {
            int g = lane + i * 32;
            if (g < NV4) {
                acc[i].x += v0[i].x + v1[i].x;
                acc[i].y += v0[i].y + v1[i].y;
                acc[i].z += v0[i].z + v1[i].z;
                acc[i].w += v0[i].w + v1[i].w;
            }
        }
    }
    if (j < e) {
        const float4* row = (const float4*)(X + (size_t)__ldg(&eidx[j]) * D);
#pragma unroll
        for (int i = 0; i < NSEG; i++) {
            int g = lane + i * 32;
            if (g < NV4) {
                float4 v = __ldg(&row[g]);
                acc[i].x += v.x; acc[i].y += v.y; acc[i].z += v.z; acc[i].w += v.w;
            }
        }
    }
    float inv = (deg > 0) ? 1.f / (float)deg : 0.f;
    float4* orow = (float4*)(outp + (size_t)node * D);
#pragma unroll
    for (int i = 0; i < NSEG; i++) {
        int g = lane + i * 32;
        if (g < NV4) {
            float4 v;
            v.x = acc[i].x * inv; v.y = acc[i].y * inv;
            v.z = acc[i].z * inv; v.w = acc[i].w * inv;
            orow[g] = v;
        }
    }
}

// ------- weight pre-pack: fp32 -> bf16 hi/lo B-fragments (mma layout) ---------
__global__ void pack_w_mma(const float* __restrict__ Wl, int K1,
                           const float* __restrict__ Wr, int K2,
                           uint4* __restrict__ out, int nsteps) {
    int idx = blockIdx.x * blockDim.x + threadIdx.x;
    if (idx >= nsteps * 1024) return;
    int lane = idx & 31, nt = (idx >> 5) & 31, s = idx >> 10;
    int g = lane >> 2, tg = lane & 3;
    int o = nt * 8 + g;
    auto getw = [&](int f) -> float {
        if (f < K1) return Wl[(size_t)f * 256 + o];
        f -= K1;
        if (f < K2) return Wr[(size_t)f * 256 + o];
        return 0.f;
    };
    int k0 = s * 16 + tg * 2;
    float w[4] = { getw(k0), getw(k0 + 1), getw(k0 + 8), getw(k0 + 9) };
    unsigned short hb[4], lb[4];
#pragma unroll
    for (int i = 0; i < 4; i++) {
        hb[i] = bf16_bits(w[i]);
        lb[i] = bf16_bits(w[i] - bf16_val(hb[i]));
    }
    uint4 r;
    r.x = ((unsigned)hb[1] << 16) | hb[0];
    r.y = ((unsigned)hb[3] << 16) | hb[2];
    r.z = ((unsigned)lb[1] << 16) | lb[0];
    r.w = ((unsigned)lb[3] << 16) | lb[2];
    out[idx] = r;
}

// ---------- bf16 mma.sync dual GEMM: C = relu([A1|A2|pad] @ W + b) ------------
// Block 64(M) x 256(N), 256 threads / 8 warps; warp w owns cols 32w..32w+31.
// Per k16-step: stage A hi/lo bf16 in smem, each warp 4(mt)x4(nt)x3 terms MMA.
// (EXACT R10/R14 measured-624.9us version.)
__global__ __launch_bounds__(256, 1)
void mma_gemm_relu(const float* __restrict__ A1, int K1,
                   const float* __restrict__ A2, int K2, int nsteps,
                   const uint4* __restrict__ Wfr,
                   const float* __restrict__ bias,
                   float* __restrict__ Cout, int M) {
    __shared__ __align__(16) unsigned short sAhi[64][16];
    __shared__ __align__(16) unsigned short sAlo[64][16];
    __shared__ float sbias[256];
    int tid = threadIdx.x;
    int wid = tid >> 5, lane = tid & 31;
    int g = lane >> 2, tg = lane & 3;
    int m0 = blockIdx.x * 64;
    sbias[tid] = bias[tid];

    float acc[4][4][4];
#pragma unroll
    for (int a = 0; a < 4; a++)
#pragma unroll
        for (int b = 0; b < 4; b++)
#pragma unroll
            for (int c = 0; c < 4; c++) acc[a][b][c] = 0.f;

    int srow = tid >> 2;           // staging row 0..63
    int kq = (tid & 3) * 4;        // staging k quad 0,4,8,12
    int grow = m0 + srow;
    bool gv = grow < M;
    const float* a1row = A1 + (size_t)grow * K1;
    const float* a2row = A2 + (size_t)grow * K2;

    for (int s = 0; s < nsteps; s++) {
        __syncthreads();           // frags of prev step consumed
        int f = s * 16 + kq;
        float4 v = make_float4(0.f, 0.f, 0.f, 0.f);
        if (gv) {
            if (f + 4 <= K1) v = *(const float4*)(a1row + f);
            else if (f >= K1 && f + 4 <= K1 + K2) v = *(const float4*)(a2row + (f - K1));
        }
        float fv[4] = { v.x, v.y, v.z, v.w };
#pragma unroll
        for (int j = 0; j < 4; j++) {
            unsigned short hb = bf16_bits(fv[j]);
            sAhi[srow][kq + j] = hb;
            sAlo[srow][kq + j] = bf16_bits(fv[j] - bf16_val(hb));
        }
        __syncthreads();

        // A fragments (PTX m16n8k16 row-major layout)
        unsigned ahi[4][4], alo[4][4];
#pragma unroll
        for (int mt = 0; mt < 4; mt++) {
            int r0 = mt * 16 + g, r1 = r0 + 8;
            ahi[mt][0] = *(const unsigned*)&sAhi[r0][tg * 2];
            ahi[mt][1] = *(const unsigned*)&sAhi[r1][tg * 2];
            ahi[mt][2] = *(const unsigned*)&sAhi[r0][tg * 2 + 8];
            ahi[mt][3] = *(const unsigned*)&sAhi[r1][tg * 2 + 8];
            alo[mt][0] = *(const unsigned*)&sAlo[r0][tg * 2];
            alo[mt][1] = *(const unsigned*)&sAlo[r1][tg * 2];
            alo[mt][2] = *(const unsigned*)&sAlo[r0][tg * 2 + 8];
            alo[mt][3] = *(const unsigned*)&sAlo[r1][tg * 2 + 8];
        }

#pragma unroll
        for (int ntl = 0; ntl < 4; ntl++) {
            int nt = wid * 4 + ntl;
            uint4 b = __ldg(&Wfr[((size_t)s * 32 + nt) * 32 + lane]);
#pragma unroll
            for (int mt = 0; mt < 4; mt++) {
                MMA16816(acc[mt][ntl], ahi[mt], b.x, b.y);   // hi @ Whi
                MMA16816(acc[mt][ntl], alo[mt], b.x, b.y);   // lo @ Whi
                MMA16816(acc[mt][ntl], ahi[mt], b.z, b.w);   // hi @ Wlo
            }
        }
    }

    // epilogue: bias + relu, fp32 out
#pragma unroll
    for (int mt = 0; mt < 4; mt++) {
        int r0 = m0 + mt * 16 + g, r1 = r0 + 8;
#pragma unroll
        for (int ntl = 0; ntl < 4; ntl++) {
            int col = (wid * 4 + ntl) * 8 + tg * 2;
            float b0 = sbias[col], b1 = sbias[col + 1];
            if (r0 < M) {
                float2 o;
                o.x = fmaxf(acc[mt][ntl][0] + b0, 0.f);
                o.y = fmaxf(acc[mt][ntl][1] + b1, 0.f);
                *(float2*)(Cout + (size_t)r0 * 256 + col) = o;
            }
            if (r1 < M) {
                float2 o;
                o.x = fmaxf(acc[mt][ntl][2] + b0, 0.f);
                o.y = fmaxf(acc[mt][ntl][3] + b1, 0.f);
                *(float2*)(Cout + (size_t)r1 * 256 + col) = o;
            }
        }
    }
}

// ---------------- final layer: small GEMM + bias + log_softmax ----------------
__global__ void final_logsoftmax(const float* __restrict__ mean2, const float* __restrict__ h1,
                                 const float* __restrict__ Wl2, const float* __restrict__ Wr2,
                                 const float* __restrict__ b2, float* __restrict__ out) {
    __shared__ float sa[DH], sb[DH], red[64];
    int row = blockIdx.x, t = threadIdx.x;
    for (int i = t; i < DH; i += 64) {
        sa[i] = mean2[(size_t)row * DH + i];
        sb[i] = h1[(size_t)row * DH + i];
    }
    __syncthreads();
    float cv = 0.f;
    if (t < DOUT) {
        cv = b2[t];
#pragma unroll 4
        for (int k = 0; k < DH; k++)
            cv = fmaf(sa[k], __ldg(&Wl2[k * DOUT + t]),
                      fmaf(sb[k], __ldg(&Wr2[k * DOUT + t]), cv));
    }
    red[t] = (t < DOUT) ? cv : -3.4e38f;
    __syncthreads();
    for (int s = 32; s > 0; s >>= 1) {
        if (t < s) red[t] = fmaxf(red[t], red[t + s]);
        __syncthreads();
    }
    float mx = red[0];
    __syncthreads();
    red[t] = (t < DOUT) ? expf(cv - mx) : 0.f;
    __syncthreads();
    for (int s = 32; s > 0; s >>= 1) {
        if (t < s) red[t] += red[t + s];
        __syncthreads();
    }
    float lse = logf(red[0]) + mx;
    if (t < DOUT) out[(size_t)row * DOUT + t] = cv - lse;
}

// ---------------- host orchestration -----------------------------------------
static inline int ceil_div(int a, int b) { return (a + b - 1) / b; }

static void build_csr(const int* src, const int* dst, int E, int n,
                      int* cnt, int* off, int* cur, int* eidx, int* csum, int* coff) {
    int nch = ceil_div(n, 1024);
    // cnt is zero on entry (invariant restored by scan_write each layer/replay)
    hist_kernel<<<ceil_div(E, 256), 256>>>(dst, E, cnt);
    scan_chunk_sum<<<nch, 256>>>(cnt, n, csum);
    scan_chunks_par<<<1, 256>>>(csum, coff, nch, off, n);
    scan_write<<<nch, 256>>>(cnt, n, coff, off, cur);
    scatter_kernel<<<ceil_div(E, 256), 256>>>(src, dst, E, cur, eidx);
}

extern "C" void kernel_launch(void* const* d_in, const int* in_sizes, int n_in,
                              void* d_out, int out_size) {
    const float* x   = (const float*)d_in[0];
    const int* src0  = (const int*)d_in[1];
    const int* dst0  = (const int*)d_in[2];
    const int* src1  = (const int*)d_in[3];
    const int* dst1  = (const int*)d_in[4];
    const int* src2  = (const int*)d_in[5];
    const int* dst2  = (const int*)d_in[6];
    const float* Wl0 = (const float*)d_in[7];
    const float* Wr0 = (const float*)d_in[8];
    const float* b0  = (const float*)d_in[9];
    const float* Wl1 = (const float*)d_in[10];
    const float* Wr1 = (const float*)d_in[11];
    const float* b1  = (const float*)d_in[12];
    const float* Wl2 = (const float*)d_in[13];
    const float* Wr2 = (const float*)d_in[14];
    const float* b2  = (const float*)d_in[15];
    float* out = (float*)d_out;

    float *mean0, *h0, *mean1, *h1, *mean2;
    int *cnt, *off, *cur, *eidx, *csum, *coff;
    uint4 *wfr0, *wfr1;
    cudaGetSymbolAddress((void**)&mean0, g_mean0);
    cudaGetSymbolAddress((void**)&h0,    g_h0);
    cudaGetSymbolAddress((void**)&mean1, g_mean1);
    cudaGetSymbolAddress((void**)&h1,    g_h1);
    cudaGetSymbolAddress((void**)&mean2, g_mean2);
    cudaGetSymbolAddress((void**)&cnt,   g_cnt);
    cudaGetSymbolAddress((void**)&off,   g_off);
    cudaGetSymbolAddress((void**)&cur,   g_cur);
    cudaGetSymbolAddress((void**)&eidx,  g_eidx);
    cudaGetSymbolAddress((void**)&csum,  g_csum);
    cudaGetSymbolAddress((void**)&coff,  g_coff);
    cudaGetSymbolAddress((void**)&wfr0,  g_wfr0);
    cudaGetSymbolAddress((void**)&wfr1,  g_wfr1);

    // weight fragment pre-pack (once per launch)
    pack_w_mma<<<ceil_div(13 * 1024, 256), 256>>>(Wl0, DIN, Wr0, DIN, wfr0, 13);
    pack_w_mma<<<ceil_div(32 * 1024, 256), 256>>>(Wl1, DH, Wr1, DH, wfr1, 32);

    // ---- layer 0 ----
    build_csr(src0, dst0, E0c, N1c, cnt, off, cur, eidx, csum, coff);
    aggregate_mean<DIN><<<ceil_div(N1c, 8), 256>>>(x, off, eidx, mean0, N1c);
    mma_gemm_relu<<<ceil_div(N1c, 64), 256>>>(mean0, DIN, x, DIN, 13, wfr0, b0, h0, N1c);

    // ---- layer 1 ----
    build_csr(src1, dst1, E1c, N2c, cnt, off, cur, eidx, csum, coff);
    aggregate_mean<DH><<<ceil_div(N2c, 8), 256>>>(h0, off, eidx, mean1, N2c);
    mma_gemm_relu<<<ceil_div(N2c, 64), 256>>>(mean1, DH, h0, DH, 32, wfr1, b1, h1, N2c);

    // ---- layer 2 + log_softmax ----
    build_csr(src2, dst2, E2c, Bc, cnt, off, cur, eidx, csum, coff);
    aggregate_mean<DH><<<ceil_div(Bc, 8), 256>>>(h1, off, eidx, mean2, Bc);
    final_logsoftmax<<<Bc, 64>>>(mean2, h1, Wl2, Wr2, b2, out);
}